// round 5
// baseline (speedup 1.0000x reference)
#include <cuda_runtime.h>
#include <math.h>

// GATTrafficPredictionModel — algebraically collapsed.
// All N=512 node features are identical (broadcast of x[:, -1, :]), so both
// GAT attention softmaxes are exactly uniform and the aggregation is the
// identity. The whole model reduces to:
//   wh[b,k,h]  = sum_f x[b,11,f] * W_heads[k,f,h]
//   hc[b,m]    = elu(wh)  (m = k*64+h)
//   who[b,c]   = sum_m hc[b,m] * W_out[m,c]
//   out[b,c]   = sum_j who[b,j] * (sum_n Wf[c, n*64+j]) + bf[c]
//
// Inputs (metadata order): x, W_heads, a1_heads, a2_heads, W_out, a1_out,
// a2_out, Wf, bf.  a1/a2 drop out exactly.

#define BB 32
#define FF 128
#define KK 8
#define HH 64
#define KH 512
#define CC 64
#define NNODE 512

__device__ float g_who[BB * CC];

// K1: 32 blocks (one per batch), 256 threads.
__global__ __launch_bounds__(256) void k1_who(
    const float* __restrict__ x,
    const float* __restrict__ W_heads,
    const float* __restrict__ W_out) {
  const int b = blockIdx.x;
  const int tid = threadIdx.x;
  __shared__ float xl[FF];
  __shared__ float hc[KH];
  __shared__ float red[256];

  if (tid < FF) xl[tid] = x[(b * 12 + 11) * FF + tid];
  __syncthreads();

  // wh + elu: each thread computes 2 of the 512 outputs.
#pragma unroll
  for (int r = 0; r < 2; r++) {
    const int m = tid + r * 256;           // m = k*64 + h
    const float* w = W_heads + (size_t)(m >> 6) * (FF * HH) + (m & 63);
    float acc = 0.f;
#pragma unroll
    for (int f = 0; f < FF; f++) acc = fmaf(xl[f], w[f * HH], acc);
    hc[m] = acc > 0.f ? acc : (expf(acc) - 1.f);
  }
  __syncthreads();

  // who[c] = hc . W_out[:, c], 4-way partial split over m.
  const int c = tid & 63;
  const int part = tid >> 6;
  float acc = 0.f;
  const float* wo = W_out + c;
#pragma unroll
  for (int i = 0; i < 128; i++) {
    const int m = part * 128 + i;
    acc = fmaf(hc[m], wo[m * CC], acc);
  }
  red[tid] = acc;
  __syncthreads();
  if (tid < 64) {
    g_who[b * CC + tid] =
        red[tid] + red[tid + 64] + red[tid + 128] + red[tid + 192];
  }
}

// K2: 64 blocks (one per output channel c), 256 threads.
// Streams Wf[c, :] (128 KB) with float4, reduces to 64 column-sums, then
// computes out[b, c] for all 32 b.
__global__ __launch_bounds__(256) void k2_final(
    const float* __restrict__ Wf,
    const float* __restrict__ bf,
    float* __restrict__ out) {
  const int c = blockIdx.x;
  const int tid = threadIdx.x;
  const int l = tid & 15;    // 16 lanes cover 64 floats (4 each)
  const int s = tid >> 4;    // 16 n-slices

  const float4* row =
      (const float4*)(Wf + (size_t)c * (NNODE * CC)) + s * 16 + l;
  float4 a = make_float4(0.f, 0.f, 0.f, 0.f);
#pragma unroll 8
  for (int i = 0; i < 32; i++) {          // n = s + 16*i, 512 total
    float4 v = row[(size_t)i * 256];
    a.x += v.x; a.y += v.y; a.z += v.z; a.w += v.w;
  }

  __shared__ float red[16][64];
  red[s][l * 4 + 0] = a.x;
  red[s][l * 4 + 1] = a.y;
  red[s][l * 4 + 2] = a.z;
  red[s][l * 4 + 3] = a.w;

  __shared__ float who_sh[BB * CC];
  for (int i = tid; i < BB * CC; i += 256) who_sh[i] = g_who[i];
  __syncthreads();

  __shared__ float sums[CC];
  if (tid < 64) {
    float t = 0.f;
#pragma unroll
    for (int s2 = 0; s2 < 16; s2++) t += red[s2][tid];
    sums[tid] = t;
  }
  __syncthreads();

  if (tid < BB) {
    float acc = bf[c];
#pragma unroll
    for (int j = 0; j < CC; j++) acc = fmaf(who_sh[tid * CC + j], sums[j], acc);
    out[tid * CC + c] = acc;
  }
}

extern "C" void kernel_launch(void* const* d_in, const int* in_sizes, int n_in,
                              void* d_out, int out_size) {
  const float* x       = (const float*)d_in[0];
  const float* W_heads = (const float*)d_in[1];
  const float* W_out   = (const float*)d_in[4];
  const float* Wf      = (const float*)d_in[7];
  const float* bf      = (const float*)d_in[8];
  float* out = (float*)d_out;

  k1_who<<<BB, 256>>>(x, W_heads, W_out);
  k2_final<<<CC, 256>>>(Wf, bf, out);
}